// round 8
// baseline (speedup 1.0000x reference)
#include <cuda_runtime.h>
#include <math.h>

#define NA     4096
#define CUTF   5.0f
#define CUT2   25.0f
#define MAGIC  12582912.0f   // 1.5*2^23 : (x+MAGIC)-MAGIC == rint-to-even(x), |x| < 2^22
#define NCMAX  1024
#define CAP    48            // per-cell capacity (lambda=8; overflow prob ~1e-20)
#define CBLK   512           // k_count blocks (8 warps x 512 = 4096 rows)

// Scratch (no device allocation allowed). Zero-init at load; g_ccnt and
// g_tick2 are restored by k_fill / k_count each call (replay-safe).
__device__ float    g_mat[18];           // [0..8] inv(box), [9..17] box
__device__ int      g_nc[3];             // cells per dim
__device__ int      g_ccnt[NCMAX];       // per-cell atom count (re-zeroed by k_fill)
__device__ float4   g_clist[NCMAX*CAP];  // per-cell lists: (x,y,z, idx-bits)
__device__ int      g_cnt[NA];           // per-row hit counts
__device__ int      g_off[NA];           // per-row exclusive offsets
__device__ int      g_total;             // total pairs
__device__ int      g_tick2;             // k_count ticket (self-resetting)
__device__ unsigned g_mask[NA * 128];    // per-row hit bitmask, ABSOLUTE j indexing

__device__ __forceinline__ int cell1d(float x, float L, int nc) {
    int c = (int)((x / L) * (float)nc);
    if (c < 0) c = 0;
    if (c >= nc) c = nc - 1;
    return c;
}

// Diagonal-box minimum image, bit-matching reference op order (validated R2-R6).
__device__ __forceinline__ float pair_d2_diag(float dx, float dy, float dz,
                                              float i0, float i1, float i2,
                                              float L0, float L1, float L2,
                                              float& ox, float& oy, float& oz) {
    float rx = __fsub_rn(__fadd_rn(__fmul_rn(dx, i0), MAGIC), MAGIC);
    float ry = __fsub_rn(__fadd_rn(__fmul_rn(dy, i1), MAGIC), MAGIC);
    float rz = __fsub_rn(__fadd_rn(__fmul_rn(dz, i2), MAGIC), MAGIC);
    ox = __fsub_rn(dx, __fmul_rn(rx, L0));
    oy = __fsub_rn(dy, __fmul_rn(ry, L1));
    oz = __fsub_rn(dz, __fmul_rn(rz, L2));
    return __fadd_rn(__fadd_rn(__fmul_rn(ox, ox), __fmul_rn(oy, oy)), __fmul_rn(oz, oz));
}

// ---------------------------------------------------------------------------
// Cell build: fully parallel, no sort. One atom per thread -> one atomicAdd
// on the cell counter + one float4 store into the fixed-capacity list.
// g_ccnt arrives zeroed (module init / previous call's k_fill).
// ---------------------------------------------------------------------------
__global__ void __launch_bounds__(256)
k_build(const float* __restrict__ pos, const float* __restrict__ box) {
    const int gid = blockIdx.x * 256 + threadIdx.x;

    if (gid == 0) {   // 3x3 inverse via cofactors (same formula as R2-R6)
        float b[9];
#pragma unroll
        for (int i = 0; i < 9; i++) b[i] = box[i];
        float c00 =  (b[4]*b[8] - b[5]*b[7]);
        float c01 = -(b[3]*b[8] - b[5]*b[6]);
        float c02 =  (b[3]*b[7] - b[4]*b[6]);
        float det = b[0]*c00 + b[1]*c01 + b[2]*c02;
        g_mat[0] = __fdiv_rn(c00, det);
        g_mat[3] = __fdiv_rn(c01, det);
        g_mat[6] = __fdiv_rn(c02, det);
        g_mat[1] = __fdiv_rn(-(b[1]*b[8] - b[2]*b[7]), det);
        g_mat[4] = __fdiv_rn( (b[0]*b[8] - b[2]*b[6]), det);
        g_mat[7] = __fdiv_rn(-(b[0]*b[7] - b[1]*b[6]), det);
        g_mat[2] = __fdiv_rn( (b[1]*b[5] - b[2]*b[4]), det);
        g_mat[5] = __fdiv_rn(-(b[0]*b[5] - b[2]*b[3]), det);
        g_mat[8] = __fdiv_rn( (b[0]*b[4] - b[1]*b[3]), det);
#pragma unroll
        for (int i = 0; i < 9; i++) g_mat[9 + i] = b[i];

        const float L0 = box[0], L1 = box[4], L2 = box[8];
        int ncx = (int)(L0 / CUTF); ncx = max(3, min(ncx, 10));
        int ncy = (int)(L1 / CUTF); ncy = max(3, min(ncy, 10));
        int ncz = (int)(L2 / CUTF); ncz = max(3, min(ncz, 10));
        g_nc[0] = ncx; g_nc[1] = ncy; g_nc[2] = ncz;
    }

    if (gid < NA) {
        const float L0 = box[0], L1 = box[4], L2 = box[8];
        int ncx = (int)(L0 / CUTF); ncx = max(3, min(ncx, 10));
        int ncy = (int)(L1 / CUTF); ncy = max(3, min(ncy, 10));
        int ncz = (int)(L2 / CUTF); ncz = max(3, min(ncz, 10));
        const float x = pos[3*gid+0], y = pos[3*gid+1], z = pos[3*gid+2];
        const int c = (cell1d(z, L2, ncz) * ncy + cell1d(y, L1, ncy)) * ncx
                      + cell1d(x, L0, ncx);
        const int n = atomicAdd(&g_ccnt[c], 1);
        if (n < CAP)
            g_clist[c * CAP + n] = make_float4(x, y, z, __int_as_float(gid));
    }
}

// ---------------------------------------------------------------------------
// COUNT pass: warp per row. For each (dz,dy), the three x-cells are flattened
// into one virtual segment so ~24 lanes stay active per iteration.
// Fused terminal scan (ticket) produces g_off / g_total / out[n_idx].
// ---------------------------------------------------------------------------
__global__ void __launch_bounds__(256)
k_count(const float* __restrict__ pos, float* __restrict__ out, int n_idx) {
    __shared__ unsigned smask[8][128];
    __shared__ int s_last;
    const int w = threadIdx.x >> 5, lane = threadIdx.x & 31;
    const int i = blockIdx.x * 8 + w;

    const float i0 = g_mat[0], i1 = g_mat[4], i2 = g_mat[8];
    const float L0 = g_mat[9], L1 = g_mat[13], L2 = g_mat[17];
    const int ncx = g_nc[0], ncy = g_nc[1], ncz = g_nc[2];
    const float xi = pos[3*i], yi = pos[3*i+1], zi = pos[3*i+2];

#pragma unroll
    for (int q = 0; q < 4; q++) smask[w][q * 32 + lane] = 0u;
    __syncwarp();

    const int cx  = cell1d(xi, L0, ncx);
    const int cy  = cell1d(yi, L1, ncy);
    const int cz  = cell1d(zi, L2, ncz);
    const int cxm = (cx == 0) ? ncx - 1 : cx - 1;
    const int cxp = (cx == ncx - 1) ? 0 : cx + 1;

    for (int dz = -1; dz <= 1; dz++) {
        int czz = cz + dz; czz += (czz < 0) ? ncz : 0; czz -= (czz >= ncz) ? ncz : 0;
        for (int dy = -1; dy <= 1; dy++) {
            int cyy = cy + dy; cyy += (cyy < 0) ? ncy : 0; cyy -= (cyy >= ncy) ? ncy : 0;
            const int rb = (czz * ncy + cyy) * ncx;
            const int ca = rb + cxm, cb = rb + cx, cc = rb + cxp;
            const int na = g_ccnt[ca];
            const int nb = g_ccnt[cb];
            const int nc_ = g_ccnt[cc];
            const int nab = na + nb, m = nab + nc_;
            for (int k = lane; k < m; k += 32) {
                int src;
                if (k < na)       src = ca * CAP + k;
                else if (k < nab) src = cb * CAP + (k - na);
                else              src = cc * CAP + (k - nab);
                const float4 p = g_clist[src];
                const int jo = __float_as_int(p.w);
                float ox, oy, oz;
                const float d2 = pair_d2_diag(xi - p.x, yi - p.y, zi - p.z,
                                              i0, i1, i2, L0, L1, L2, ox, oy, oz);
                if (jo > i && d2 < CUT2)
                    atomicOr(&smask[w][jo >> 5], 1u << (jo & 31));
            }
        }
    }
    __syncwarp();

    uint4 mv = make_uint4(smask[w][4*lane], smask[w][4*lane+1],
                          smask[w][4*lane+2], smask[w][4*lane+3]);
    ((uint4*)(g_mask + (size_t)i * 128))[lane] = mv;
    int c = __popc(mv.x) + __popc(mv.y) + __popc(mv.z) + __popc(mv.w);
    c = __reduce_add_sync(0xffffffffu, c);
    if (lane == 0) g_cnt[i] = c;

    // -------- fused terminal scan --------
    __syncthreads();
    __threadfence();
    if (threadIdx.x == 0)
        s_last = (atomicAdd(&g_tick2, 1) == CBLK - 1);
    __syncthreads();
    if (!s_last) return;
    __threadfence();

    __shared__ int wsum[8];
    const int t = threadIdx.x;
    int cv[16], s = 0;
#pragma unroll
    for (int k = 0; k < 16; k++) { cv[k] = g_cnt[16 * t + k]; s += cv[k]; }
    int incl = s;
#pragma unroll
    for (int d = 1; d < 32; d <<= 1) {
        int u = __shfl_up_sync(0xffffffffu, incl, d);
        if (lane >= d) incl += u;
    }
    if (lane == 31) wsum[w] = incl;
    __syncthreads();
    int wbase = 0;
#pragma unroll
    for (int q = 0; q < 8; q++) wbase += (q < w) ? wsum[q] : 0;
    int run = wbase + incl - s;
#pragma unroll
    for (int k = 0; k < 16; k++) { g_off[16 * t + k] = run; run += cv[k]; }
    if (t == 255) { g_total = run; out[n_idx] = (float)run; }
    if (t == 0) g_tick2 = 0;          // restore ticket for next call
}

// ---------------------------------------------------------------------------
// FILL pass: warp per row, uint4 mask load, one warp scan, serial emit.
// Contiguous tail padding + g_ccnt reset (for next call) folded in.
// ---------------------------------------------------------------------------
__global__ void __launch_bounds__(256)
k_fill(const float* __restrict__ pos, float* __restrict__ out, int P) {
    const int w = threadIdx.x >> 5, lane = threadIdx.x & 31;
    const int i = blockIdx.x * 8 + w;             // 512 blocks x 8 warps

    // block 0: reset per-cell counters for the next launch (consumed only by
    // the next call's k_build; kernel boundary orders this correctly)
    if (blockIdx.x == 0)
        for (int k = threadIdx.x; k < NCMAX; k += 256) g_ccnt[k] = 0;

    const float i0 = g_mat[0], i1 = g_mat[4], i2 = g_mat[8];
    const float L0 = g_mat[9], L1 = g_mat[13], L2 = g_mat[17];
    const float xi = pos[3*i], yi = pos[3*i+1], zi = pos[3*i+2];

    const uint4 mv = ((const uint4*)(g_mask + (size_t)i * 128))[lane];
    const int c = __popc(mv.x) + __popc(mv.y) + __popc(mv.z) + __popc(mv.w);
    int incl = c;
#pragma unroll
    for (int d = 1; d < 32; d <<= 1) {
        int u = __shfl_up_sync(0xffffffffu, incl, d);
        if (lane >= d) incl += u;
    }
    int idx = g_off[i] + incl - c;

    unsigned ws[4] = {mv.x, mv.y, mv.z, mv.w};
#pragma unroll
    for (int q = 0; q < 4; q++) {
        unsigned wv = ws[q];
        while (wv) {
            const int b = __ffs(wv) - 1; wv &= (wv - 1);
            const int j = 128 * lane + 32 * q + b;
            float ox, oy, oz;
            const float d2 = pair_d2_diag(xi - __ldg(pos + 3*j),
                                          yi - __ldg(pos + 3*j + 1),
                                          zi - __ldg(pos + 3*j + 2),
                                          i0, i1, i2, L0, L1, L2, ox, oy, oz);
            out[idx]             = (float)i;
            out[(size_t)P + idx] = (float)j;
            float* dp = out + (size_t)2 * P + 3 * (size_t)idx;
            dp[0] = ox; dp[1] = oy; dp[2] = oz;
            out[(size_t)5 * P + idx] = sqrtf(d2);
            idx++;
        }
    }

    // ---- contiguous tail padding ----
    const int total = g_total;
    const int tid   = blockIdx.x * blockDim.x + threadIdx.x;
    const int nthr  = gridDim.x * blockDim.x;
    const int tail  = P - total;
    for (int k = tid; k < tail; k += nthr) {
        out[total + k]             = -1.0f;
        out[(size_t)P + total + k] = -1.0f;
    }
    const int dtail = 3 * tail;
    float* dbase = out + (size_t)2 * P + 3 * (size_t)total;
    for (int k = tid; k < dtail; k += nthr) dbase[k] = 0.0f;
    for (int k = tid; k < tail; k += nthr)
        out[(size_t)5 * P + total + k] = 0.0f;
}

extern "C" void kernel_launch(void* const* d_in, const int* in_sizes, int n_in,
                              void* d_out, int out_size) {
    const float* pos = (const float*)d_in[0];   // [4096, 3] float32
    const float* box = (const float*)d_in[1];   // [3, 3]   float32
    float* out = (float*)d_out;
    const int P = (out_size - 1) / 6;           // MAX_NUM_PAIRS

    k_build<<<16, 256>>>(pos, box);             // parallel capacity-list build
    k_count<<<CBLK, 256>>>(pos, out, 6 * P);    // bitmasks + fused scan/n_pairs
    k_fill<<<512, 256>>>(pos, out, P);          // ordered fill + padding + reset
}

// round 9
// speedup vs baseline: 1.3243x; 1.3243x over previous
#include <cuda_runtime.h>
#include <math.h>

#define NA     4096
#define CUTF   5.0f
#define CUT2   25.0f
#define MAGIC  12582912.0f   // 1.5*2^23 : (x+MAGIC)-MAGIC == rint-to-even(x), |x| < 2^22
#define NCMAX  1024
#define CAP    48            // per-cell capacity (lambda=8; overflow prob ~1e-20)
#define NB     128           // blocks (all co-resident: >=1 block/SM on 148 SMs)
#define NT     512           // threads per block -> 2048 warps total

// Scratch (no device allocation). Zero-init at load; g_ccnt is re-zeroed and
// g_bar returns to 0 inside each call; g_gen only ever compared relatively.
__device__ float        g_mat[18];           // [0..8] inv(box), [9..17] box
__device__ int          g_ccnt[NCMAX];       // per-cell atom count
__device__ float4       g_clist[NCMAX*CAP];  // per-cell lists: (x,y,z, idx-bits)
__device__ int          g_cnt[NA];           // per-row hit counts
__device__ int          g_bar;               // barrier arrival counter
__device__ volatile int g_gen;               // barrier generation (L1-bypassed)
__device__ unsigned     g_mask[NA * 128];    // per-row hit bitmask, ABSOLUTE j

__device__ __forceinline__ int cell1d(float x, float L, int nc) {
    int c = (int)((x / L) * (float)nc);
    if (c < 0) c = 0;
    if (c >= nc) c = nc - 1;
    return c;
}

// Diagonal-box minimum image, bit-matching reference op order (validated R2-R7).
__device__ __forceinline__ float pair_d2_diag(float dx, float dy, float dz,
                                              float i0, float i1, float i2,
                                              float L0, float L1, float L2,
                                              float& ox, float& oy, float& oz) {
    float rx = __fsub_rn(__fadd_rn(__fmul_rn(dx, i0), MAGIC), MAGIC);
    float ry = __fsub_rn(__fadd_rn(__fmul_rn(dy, i1), MAGIC), MAGIC);
    float rz = __fsub_rn(__fadd_rn(__fmul_rn(dz, i2), MAGIC), MAGIC);
    ox = __fsub_rn(dx, __fmul_rn(rx, L0));
    oy = __fsub_rn(dy, __fmul_rn(ry, L1));
    oz = __fsub_rn(dz, __fmul_rn(rz, L2));
    return __fadd_rn(__fadd_rn(__fmul_rn(ox, ox), __fmul_rn(oy, oy)), __fmul_rn(oz, oz));
}

// Sense-reversing grid barrier. Writers fence before arriving; last block
// fences then bumps the generation; spinners poll the volatile generation.
__device__ __forceinline__ void gbar() {
    __syncthreads();
    if (threadIdx.x == 0) {
        __threadfence();
        const int gen = g_gen;
        if (atomicAdd(&g_bar, 1) == NB - 1) {
            g_bar = 0;
            __threadfence();
            g_gen = gen + 1;
        } else {
            while (g_gen == gen) __nanosleep(64);
        }
    }
    __syncthreads();
}

__global__ void __launch_bounds__(NT)
k_all(const float* __restrict__ pos, const float* __restrict__ box,
      float* __restrict__ out, int P) {
    __shared__ unsigned smask[16][128];   // 8 KB  per-warp row mask staging
    __shared__ int      spref[16][32];    // 2 KB  27-cell inclusive prefix
    __shared__ int      sbase[16][32];    // 2 KB  27-cell list base offsets
    __shared__ int      soff[NA];         // 16 KB row offsets (block-local scan)
    __shared__ int      swsum[16];
    __shared__ int      s_total;

    const int tid  = threadIdx.x, bid = blockIdx.x;
    const int gid  = bid * NT + tid;
    const int w    = tid >> 5, lane = tid & 31;
    const int gw   = bid * 16 + w;        // global warp id [0, 2048)

    // ================= Phase A: build capacity cell lists =================
    if (gid == 0) {   // 3x3 inverse via cofactors (same formula as R2-R7)
        float b[9];
#pragma unroll
        for (int i = 0; i < 9; i++) b[i] = box[i];
        float c00 =  (b[4]*b[8] - b[5]*b[7]);
        float c01 = -(b[3]*b[8] - b[5]*b[6]);
        float c02 =  (b[3]*b[7] - b[4]*b[6]);
        float det = b[0]*c00 + b[1]*c01 + b[2]*c02;
        g_mat[0] = __fdiv_rn(c00, det);
        g_mat[3] = __fdiv_rn(c01, det);
        g_mat[6] = __fdiv_rn(c02, det);
        g_mat[1] = __fdiv_rn(-(b[1]*b[8] - b[2]*b[7]), det);
        g_mat[4] = __fdiv_rn( (b[0]*b[8] - b[2]*b[6]), det);
        g_mat[7] = __fdiv_rn(-(b[0]*b[7] - b[1]*b[6]), det);
        g_mat[2] = __fdiv_rn( (b[1]*b[5] - b[2]*b[4]), det);
        g_mat[5] = __fdiv_rn(-(b[0]*b[5] - b[2]*b[3]), det);
        g_mat[8] = __fdiv_rn( (b[0]*b[4] - b[1]*b[3]), det);
#pragma unroll
        for (int i = 0; i < 9; i++) g_mat[9 + i] = b[i];
    }

    const float L0 = box[0], L1 = box[4], L2 = box[8];
    int ncx = (int)(L0 / CUTF); ncx = max(3, min(ncx, 10));
    int ncy = (int)(L1 / CUTF); ncy = max(3, min(ncy, 10));
    int ncz = (int)(L2 / CUTF); ncz = max(3, min(ncz, 10));

    if (gid < NA) {
        const float x = pos[3*gid+0], y = pos[3*gid+1], z = pos[3*gid+2];
        const int c = (cell1d(z, L2, ncz) * ncy + cell1d(y, L1, ncy)) * ncx
                      + cell1d(x, L0, ncx);
        const int n = atomicAdd(&g_ccnt[c], 1);
        if (n < CAP)
            g_clist[c * CAP + n] = make_float4(x, y, z, __int_as_float(gid));
    }
    gbar();

    // ================= Phase B: count rows -> bitmask + g_cnt ==============
    const float i0 = g_mat[0], i1 = g_mat[4], i2 = g_mat[8];

#pragma unroll
    for (int r = 0; r < 2; r++) {
        const int row = 2 * gw + r;
        const float xi = pos[3*row], yi = pos[3*row+1], zi = pos[3*row+2];
        const int cx = cell1d(xi, L0, ncx);
        const int cy = cell1d(yi, L1, ncy);
        const int cz = cell1d(zi, L2, ncz);

        // lanes 0..26: one neighbor cell each -> parallel count loads
        int n27 = 0, b27 = 0;
        if (lane < 27) {
            int dz = lane / 9 - 1, dy = (lane / 3) % 3 - 1, dx = lane % 3 - 1;
            int czz = cz + dz; czz += (czz < 0) ? ncz : 0; czz -= (czz >= ncz) ? ncz : 0;
            int cyy = cy + dy; cyy += (cyy < 0) ? ncy : 0; cyy -= (cyy >= ncy) ? ncy : 0;
            int cxx = cx + dx; cxx += (cxx < 0) ? ncx : 0; cxx -= (cxx >= ncx) ? ncx : 0;
            const int c = (czz * ncy + cyy) * ncx + cxx;
            n27 = min(g_ccnt[c], CAP);
            b27 = c * CAP;
        }
        int pref = n27;
#pragma unroll
        for (int d = 1; d < 32; d <<= 1) {
            int u = __shfl_up_sync(0xffffffffu, pref, d);
            if (lane >= d) pref += u;
        }
        spref[w][lane] = pref;                    // lanes >= 27 hold M
        sbase[w][lane] = b27;
        const int M = __shfl_sync(0xffffffffu, pref, 31);

#pragma unroll
        for (int q = 0; q < 4; q++) smask[w][q * 32 + lane] = 0u;
        __syncwarp();

        for (int k = lane; k < M; k += 32) {      // ~7 fully-occupied iters
            int lo = 0, hi = 26;                  // binary search: pref[s] > k
            while (lo < hi) {
                const int mid = (lo + hi) >> 1;
                if (spref[w][mid] > k) hi = mid; else lo = mid + 1;
            }
            const int off = k - ((lo > 0) ? spref[w][lo - 1] : 0);
            const float4 p = g_clist[sbase[w][lo] + off];
            const int jo = __float_as_int(p.w);
            float ox, oy, oz;
            const float d2 = pair_d2_diag(xi - p.x, yi - p.y, zi - p.z,
                                          i0, i1, i2, L0, L1, L2, ox, oy, oz);
            if (jo > row && d2 < CUT2)
                atomicOr(&smask[w][jo >> 5], 1u << (jo & 31));
        }
        __syncwarp();

        uint4 mv = make_uint4(smask[w][4*lane], smask[w][4*lane+1],
                              smask[w][4*lane+2], smask[w][4*lane+3]);
        ((uint4*)(g_mask + (size_t)row * 128))[lane] = mv;
        int c = __popc(mv.x) + __popc(mv.y) + __popc(mv.z) + __popc(mv.w);
        c = __reduce_add_sync(0xffffffffu, c);
        if (lane == 0) g_cnt[row] = c;
    }
    gbar();

    // ========== Phase C: block-redundant exclusive scan of g_cnt ==========
    {
        int cv[8], s = 0;
#pragma unroll
        for (int k = 0; k < 8; k++) { cv[k] = __ldcg(&g_cnt[8 * tid + k]); s += cv[k]; }
        int incl = s;
#pragma unroll
        for (int d = 1; d < 32; d <<= 1) {
            int u = __shfl_up_sync(0xffffffffu, incl, d);
            if (lane >= d) incl += u;
        }
        if (lane == 31) swsum[w] = incl;
        __syncthreads();
        if (w == 0 && lane < 16) {
            int wv = swsum[lane], wincl = wv;
#pragma unroll
            for (int d = 1; d < 16; d <<= 1) {
                int u = __shfl_up_sync(0x0000ffffu, wincl, d);
                if (lane >= d) wincl += u;
            }
            swsum[lane] = wincl - wv;
        }
        __syncthreads();
        int run = swsum[w] + incl - s;
#pragma unroll
        for (int k = 0; k < 8; k++) { soff[8 * tid + k] = run; run += cv[k]; }
        if (tid == NT - 1) {
            s_total = run;
            if (bid == 0) out[6 * P] = (float)run;     // n_pairs
        }
        __syncthreads();
    }
    const int total = s_total;

    // ================= Phase D: ordered fill + padding + reset ============
    if (gid < NCMAX) g_ccnt[gid] = 0;   // restore for next graph replay

#pragma unroll
    for (int r = 0; r < 2; r++) {
        const int row = 2 * gw + r;
        const float xi = pos[3*row], yi = pos[3*row+1], zi = pos[3*row+2];
        const uint4 mv = ((const uint4*)(g_mask + (size_t)row * 128))[lane];
        const int c = __popc(mv.x) + __popc(mv.y) + __popc(mv.z) + __popc(mv.w);
        int incl = c;
#pragma unroll
        for (int d = 1; d < 32; d <<= 1) {
            int u = __shfl_up_sync(0xffffffffu, incl, d);
            if (lane >= d) incl += u;
        }
        int idx = soff[row] + incl - c;

        unsigned wsv[4] = {mv.x, mv.y, mv.z, mv.w};
#pragma unroll
        for (int q = 0; q < 4; q++) {
            unsigned wv = wsv[q];
            while (wv) {
                const int b = __ffs(wv) - 1; wv &= (wv - 1);
                const int j = 128 * lane + 32 * q + b;
                float ox, oy, oz;
                const float d2 = pair_d2_diag(xi - __ldg(pos + 3*j),
                                              yi - __ldg(pos + 3*j + 1),
                                              zi - __ldg(pos + 3*j + 2),
                                              i0, i1, i2, L0, L1, L2, ox, oy, oz);
                out[idx]             = (float)row;
                out[(size_t)P + idx] = (float)j;
                float* dp = out + (size_t)2 * P + 3 * (size_t)idx;
                dp[0] = ox; dp[1] = oy; dp[2] = oz;
                out[(size_t)5 * P + idx] = sqrtf(d2);
                idx++;
            }
        }
    }

    // contiguous tail padding (regions disjoint from hit writes)
    const int nthr = NB * NT;
    const int tail = P - total;
    for (int k = gid; k < tail; k += nthr) {
        out[total + k]             = -1.0f;
        out[(size_t)P + total + k] = -1.0f;
    }
    const int dtail = 3 * tail;
    float* dbase = out + (size_t)2 * P + 3 * (size_t)total;
    for (int k = gid; k < dtail; k += nthr) dbase[k] = 0.0f;
    for (int k = gid; k < tail; k += nthr)
        out[(size_t)5 * P + total + k] = 0.0f;
}

extern "C" void kernel_launch(void* const* d_in, const int* in_sizes, int n_in,
                              void* d_out, int out_size) {
    const float* pos = (const float*)d_in[0];   // [4096, 3] float32
    const float* box = (const float*)d_in[1];   // [3, 3]   float32
    float* out = (float*)d_out;
    const int P = (out_size - 1) / 6;           // MAX_NUM_PAIRS

    k_all<<<NB, NT>>>(pos, box, out, P);        // fused: build|count|scan|fill
}